// round 1
// baseline (speedup 1.0000x reference)
#include <cuda_runtime.h>

#define NC   21
#define NC2  (NC * NC)
#define NB   8
#define HW   (512 * 512)
#define Q    (HW / 4)            // float4 groups per channel plane

// Scratch: per-sample confusion matrices conf[b][true][pred]
__device__ int g_conf[NB * NC2];

__global__ void zero_conf_kernel() {
    int i = blockIdx.x * blockDim.x + threadIdx.x;
    if (i < NB * NC2) g_conf[i] = 0;
}

__global__ void conf_kernel(const float* __restrict__ pred,
                            const float* __restrict__ tgt) {
    __shared__ int sconf[NC2];
    for (int i = threadIdx.x; i < NC2; i += blockDim.x) sconf[i] = 0;
    __syncthreads();

    int tid = blockIdx.x * blockDim.x + threadIdx.x;   // < NB*Q = 524288
    int b = tid / Q;          // uniform within a block (Q % 256 == 0)
    int p = tid - b * Q;

    const float4* pp = reinterpret_cast<const float4*>(pred) + (size_t)b * NC * Q + p;
    const float4* tp = reinterpret_cast<const float4*>(tgt)  + (size_t)b * NC * Q + p;

    float4 pm = pp[0];
    float4 tm = tp[0];
    int pax = 0, pay = 0, paz = 0, paw = 0;
    int tax = 0, tay = 0, taz = 0, taw = 0;

    #pragma unroll
    for (int c = 1; c < NC; c++) {
        float4 v = pp[(size_t)c * Q];
        float4 w = tp[(size_t)c * Q];
        if (v.x > pm.x) { pm.x = v.x; pax = c; }
        if (v.y > pm.y) { pm.y = v.y; pay = c; }
        if (v.z > pm.z) { pm.z = v.z; paz = c; }
        if (v.w > pm.w) { pm.w = v.w; paw = c; }
        if (w.x > tm.x) { tm.x = w.x; tax = c; }
        if (w.y > tm.y) { tm.y = w.y; tay = c; }
        if (w.z > tm.z) { tm.z = w.z; taz = c; }
        if (w.w > tm.w) { tm.w = w.w; taw = c; }
    }

    atomicAdd(&sconf[tax * NC + pax], 1);
    atomicAdd(&sconf[tay * NC + pay], 1);
    atomicAdd(&sconf[taz * NC + paz], 1);
    atomicAdd(&sconf[taw * NC + paw], 1);

    __syncthreads();
    for (int i = threadIdx.x; i < NC2; i += blockDim.x) {
        int v = sconf[i];
        if (v) atomicAdd(&g_conf[b * NC2 + i], v);
    }
}

__global__ void finalize_kernel(float* __restrict__ out) {
    __shared__ float iou_sum[NB];
    __shared__ int   valid_cnt[NB];
    int t = threadIdx.x;
    if (t < NB) { iou_sum[t] = 0.0f; valid_cnt[t] = 0; }
    __syncthreads();

    if (t < NB * NC) {
        int b = t / NC;
        int c = t - b * NC;
        const int* cb = &g_conf[b * NC2];
        int tp  = cb[c * NC + c];
        int row = 0, col = 0;
        #pragma unroll
        for (int k = 0; k < NC; k++) {
            row += cb[c * NC + k];   // TP + FN
            col += cb[k * NC + c];   // TP + FP
        }
        if (tp > 0) {
            float iou = (float)tp / (float)(row + col - tp);
            atomicAdd(&iou_sum[b], iou);
            atomicAdd(&valid_cnt[b], 1);
        }
    }
    __syncthreads();

    if (t == 0) {
        float s = 0.0f;
        #pragma unroll
        for (int b = 0; b < NB; b++)
            s += iou_sum[b] / fmaxf((float)valid_cnt[b], 1.0f);
        out[0] = s / (float)NB;
    }
}

extern "C" void kernel_launch(void* const* d_in, const int* in_sizes, int n_in,
                              void* d_out, int out_size) {
    const float* pred = (const float*)d_in[0];
    const float* tgt  = (const float*)d_in[1];
    float* out = (float*)d_out;

    zero_conf_kernel<<<(NB * NC2 + 255) / 256, 256>>>();
    conf_kernel<<<(NB * Q) / 256, 256>>>(pred, tgt);
    finalize_kernel<<<1, 256>>>(out);
}

// round 2
// speedup vs baseline: 1.0437x; 1.0437x over previous
#include <cuda_runtime.h>

#define NC   21
#define NC2  (NC * NC)
#define NB   8
#define HW   (512 * 512)
#define Q    (HW / 4)            // float4 groups per channel plane

// Scratch: per-sample confusion matrices conf[b][true][pred].
// Zero-initialized at module load; finalize_kernel re-zeroes it after each
// use, so every kernel_launch invocation starts from a clean state.
__device__ int g_conf[NB * NC2];

__global__ void conf_kernel(const float* __restrict__ pred,
                            const float* __restrict__ tgt) {
    __shared__ int sconf[NC2];
    for (int i = threadIdx.x; i < NC2; i += blockDim.x) sconf[i] = 0;
    __syncthreads();

    int tid = blockIdx.x * blockDim.x + threadIdx.x;   // < NB*Q = 524288
    int b = tid / Q;          // uniform within a block (Q % 256 == 0)
    int p = tid - b * Q;

    const float4* pp = reinterpret_cast<const float4*>(pred) + (size_t)b * NC * Q + p;
    const float4* tp = reinterpret_cast<const float4*>(tgt)  + (size_t)b * NC * Q + p;

    float4 pm = __ldcs(pp);
    float4 tm = __ldcs(tp);
    int pax = 0, pay = 0, paz = 0, paw = 0;
    int tax = 0, tay = 0, taz = 0, taw = 0;

    #pragma unroll
    for (int c = 1; c < NC; c++) {
        float4 v = __ldcs(pp + (size_t)c * Q);
        float4 w = __ldcs(tp + (size_t)c * Q);
        if (v.x > pm.x) { pm.x = v.x; pax = c; }
        if (v.y > pm.y) { pm.y = v.y; pay = c; }
        if (v.z > pm.z) { pm.z = v.z; paz = c; }
        if (v.w > pm.w) { pm.w = v.w; paw = c; }
        if (w.x > tm.x) { tm.x = w.x; tax = c; }
        if (w.y > tm.y) { tm.y = w.y; tay = c; }
        if (w.z > tm.z) { tm.z = w.z; taz = c; }
        if (w.w > tm.w) { tm.w = w.w; taw = c; }
    }

    atomicAdd(&sconf[tax * NC + pax], 1);
    atomicAdd(&sconf[tay * NC + pay], 1);
    atomicAdd(&sconf[taz * NC + paz], 1);
    atomicAdd(&sconf[taw * NC + paw], 1);

    __syncthreads();
    for (int i = threadIdx.x; i < NC2; i += blockDim.x) {
        int v = sconf[i];
        if (v) atomicAdd(&g_conf[b * NC2 + i], v);
    }
}

__global__ void finalize_kernel(float* __restrict__ out) {
    __shared__ float iou_sum[NB];
    __shared__ int   valid_cnt[NB];
    int t = threadIdx.x;
    if (t < NB) { iou_sum[t] = 0.0f; valid_cnt[t] = 0; }
    __syncthreads();

    if (t < NB * NC) {
        int b = t / NC;
        int c = t - b * NC;
        const int* cb = &g_conf[b * NC2];
        int tp  = cb[c * NC + c];
        int row = 0, col = 0;
        #pragma unroll
        for (int k = 0; k < NC; k++) {
            row += cb[c * NC + k];   // TP + FN
            col += cb[k * NC + c];   // TP + FP
        }
        if (tp > 0) {
            float iou = (float)tp / (float)(row + col - tp);
            atomicAdd(&iou_sum[b], iou);
            atomicAdd(&valid_cnt[b], 1);
        }
    }
    __syncthreads();

    // Re-zero scratch for the next invocation (all reads are done above).
    for (int i = t; i < NB * NC2; i += blockDim.x) g_conf[i] = 0;

    if (t == 0) {
        float s = 0.0f;
        #pragma unroll
        for (int b = 0; b < NB; b++)
            s += iou_sum[b] / fmaxf((float)valid_cnt[b], 1.0f);
        out[0] = s / (float)NB;
    }
}

extern "C" void kernel_launch(void* const* d_in, const int* in_sizes, int n_in,
                              void* d_out, int out_size) {
    const float* pred = (const float*)d_in[0];
    const float* tgt  = (const float*)d_in[1];
    float* out = (float*)d_out;

    conf_kernel<<<(NB * Q) / 256, 256>>>(pred, tgt);
    finalize_kernel<<<1, 256>>>(out);
}

// round 3
// speedup vs baseline: 1.0501x; 1.0061x over previous
#include <cuda_runtime.h>

#define NC   21
#define NC2  (NC * NC)
#define NB   8
#define HW   (512 * 512)
#define Q    (HW / 4)            // float4 groups per channel plane
#define NBLOCKS ((NB * Q) / 256) // 2048

// Scratch: per-sample confusion matrices conf[b][true][pred].
// Zero at module load; the last block of each invocation re-zeroes after use.
__device__ int g_conf[NB * NC2];
__device__ unsigned int g_done;   // zero-init; reset by last block each run

__global__ void conf_kernel(const float* __restrict__ pred,
                            const float* __restrict__ tgt,
                            float* __restrict__ out) {
    __shared__ int sconf[NC2];
    for (int i = threadIdx.x; i < NC2; i += blockDim.x) sconf[i] = 0;
    __syncthreads();

    int tid = blockIdx.x * blockDim.x + threadIdx.x;   // < NB*Q = 524288
    int b = tid / Q;          // uniform within a block (Q % 256 == 0)
    int p = tid - b * Q;

    const float4* pp = reinterpret_cast<const float4*>(pred) + (size_t)b * NC * Q + p;
    const float4* tp = reinterpret_cast<const float4*>(tgt)  + (size_t)b * NC * Q + p;

    float4 pm = __ldcs(pp);
    float4 tm = __ldcs(tp);
    int pax = 0, pay = 0, paz = 0, paw = 0;
    int tax = 0, tay = 0, taz = 0, taw = 0;

    #pragma unroll
    for (int c = 1; c < NC; c++) {
        float4 v = __ldcs(pp + (size_t)c * Q);
        float4 w = __ldcs(tp + (size_t)c * Q);
        if (v.x > pm.x) { pm.x = v.x; pax = c; }
        if (v.y > pm.y) { pm.y = v.y; pay = c; }
        if (v.z > pm.z) { pm.z = v.z; paz = c; }
        if (v.w > pm.w) { pm.w = v.w; paw = c; }
        if (w.x > tm.x) { tm.x = w.x; tax = c; }
        if (w.y > tm.y) { tm.y = w.y; tay = c; }
        if (w.z > tm.z) { tm.z = w.z; taz = c; }
        if (w.w > tm.w) { tm.w = w.w; taw = c; }
    }

    atomicAdd(&sconf[tax * NC + pax], 1);
    atomicAdd(&sconf[tay * NC + pay], 1);
    atomicAdd(&sconf[taz * NC + paz], 1);
    atomicAdd(&sconf[taw * NC + paw], 1);

    __syncthreads();
    for (int i = threadIdx.x; i < NC2; i += blockDim.x) {
        int v = sconf[i];
        if (v) atomicAdd(&g_conf[b * NC2 + i], v);
    }

    // ---- last-block finalize ----
    __threadfence();
    __shared__ unsigned int s_rank;
    if (threadIdx.x == 0) s_rank = atomicAdd(&g_done, 1u);
    __syncthreads();
    if (s_rank != NBLOCKS - 1) return;

    // This is the last block: all g_conf atomics are visible (L2-coherent).
    __shared__ float iou_sum[NB];
    __shared__ int   valid_cnt[NB];
    int t = threadIdx.x;
    if (t < NB) { iou_sum[t] = 0.0f; valid_cnt[t] = 0; }
    if (t == 0) g_done = 0;                 // reset for next invocation
    __syncthreads();

    if (t < NB * NC) {
        int bb = t / NC;
        int c  = t - bb * NC;
        const int* cb = &g_conf[bb * NC2];
        int tpv = __ldcg(&cb[c * NC + c]);
        int row = 0, col = 0;
        #pragma unroll
        for (int k = 0; k < NC; k++) {
            row += __ldcg(&cb[c * NC + k]);   // TP + FN
            col += __ldcg(&cb[k * NC + c]);   // TP + FP
        }
        if (tpv > 0) {
            float iou = (float)tpv / (float)(row + col - tpv);
            atomicAdd(&iou_sum[bb], iou);
            atomicAdd(&valid_cnt[bb], 1);
        }
    }
    __syncthreads();

    // Re-zero scratch for the next invocation (all reads done above).
    for (int i = t; i < NB * NC2; i += blockDim.x) g_conf[i] = 0;

    if (t == 0) {
        float s = 0.0f;
        #pragma unroll
        for (int bb = 0; bb < NB; bb++)
            s += iou_sum[bb] / fmaxf((float)valid_cnt[bb], 1.0f);
        out[0] = s / (float)NB;
    }
}

extern "C" void kernel_launch(void* const* d_in, const int* in_sizes, int n_in,
                              void* d_out, int out_size) {
    const float* pred = (const float*)d_in[0];
    const float* tgt  = (const float*)d_in[1];
    float* out = (float*)d_out;

    conf_kernel<<<NBLOCKS, 256>>>(pred, tgt, out);
}